// round 15
// baseline (speedup 1.0000x reference)
#include <cuda_runtime.h>
#include <cstdint>

#define NN 100000
#define NE 800000
#define HID 256
#define BN 32

typedef unsigned long long u64;

// Scratch (allocation-free rule: __device__ globals). 16B-aligned for float4 access.
__device__ __align__(16) float g_dinv[NN];
__device__ __align__(16) float g_hs[NN * BN];     // row-prescaled features
__device__ __align__(16) float g_agg[NN * BN];    // aggregation accumulator

// ---- f32x2 packed helpers -------------------------------------------------
__device__ __forceinline__ u64 pk2(float lo, float hi) {
    u64 r; asm("mov.b64 %0, {%1, %2};" : "=l"(r) : "f"(lo), "f"(hi)); return r;
}
__device__ __forceinline__ void upk2(float& lo, float& hi, u64 v) {
    asm("mov.b64 {%0, %1}, %2;" : "=f"(lo), "=f"(hi) : "l"(v));
}
__device__ __forceinline__ void ffma2(u64& d, u64 a, u64 b) {
    asm("fma.rn.f32x2 %0, %1, %2, %0;" : "+l"(d) : "l"(a), "l"(b));
}

// ---- cp.async helpers -----------------------------------------------------
__device__ __forceinline__ void cpa16(uint32_t d, const void* s) {
    asm volatile("cp.async.cg.shared.global [%0], [%1], 16;" :: "r"(d), "l"(s) : "memory");
}
__device__ __forceinline__ void cpa4(uint32_t d, const void* s) {
    asm volatile("cp.async.ca.shared.global [%0], [%1], 4;" :: "r"(d), "l"(s) : "memory");
}
#define CP_COMMIT() asm volatile("cp.async.commit_group;" ::: "memory")
#define CP_WAIT0()  asm volatile("cp.async.wait_group 0;" ::: "memory")
#define CP_WAIT1()  asm volatile("cp.async.wait_group 1;" ::: "memory")

// ---------------------------------------------------------------------------
// Degree / normalization
// ---------------------------------------------------------------------------
__global__ void k_init_deg() {
    int i = blockIdx.x * blockDim.x + threadIdx.x;
    if (i < NN) g_dinv[i] = 1.0f;     // self-loop contributes 1 to every degree
}

__global__ __launch_bounds__(256) void k_count_deg(const int* __restrict__ col) {
    for (int e = blockIdx.x * blockDim.x + threadIdx.x; e < NE;
         e += gridDim.x * blockDim.x)
        atomicAdd(&g_dinv[col[e]], 1.0f);
}

__global__ void k_finalize_dinv() {
    int i = blockIdx.x * blockDim.x + threadIdx.x;
    if (i < NN) g_dinv[i] = rsqrtf(g_dinv[i]);   // deg >= 1 always
}

// ---------------------------------------------------------------------------
// GEMM1 (R9 version, measured 49.7us): hs = (x @ Wd^T)*dinv; agg = hs*dinv
// 128 rows/block, 128 threads, 8x4 tile (f32x2), cp.async double buffer.
// Rows ry + 16*i, stride-36 rows -> banks 4 apart: conflict-free a-loads.
// ---------------------------------------------------------------------------
__global__ __launch_bounds__(128) void k_gemm_down(const float* __restrict__ x,
                                                   const float* __restrict__ Wd) {
    __shared__ __align__(16) float As[2][128 * 36];  // 36,864 B
    __shared__ __align__(16) float Bs[2][32 * 36];   //  9,216 B  (total 46,080)

    int tid = threadIdx.x;
    int cx = tid & 7;                 // 8 col-groups * 4 = 32 cols
    int ry = tid >> 3;                // 0..15; rows ry + 16*i
    int rowbase = blockIdx.x * 128;

    uint32_t as0 = (uint32_t)__cvta_generic_to_shared(&As[0][0]);
    uint32_t bs0 = (uint32_t)__cvta_generic_to_shared(&Bs[0][0]);

    // stage chunk ch into buffer buf (async)
    auto stage = [&](int ch, int buf) {
        int hbase = ch * 32;
        uint32_t asb = as0 + buf * (128 * 36 * 4);
        uint32_t bsb = bs0 + buf * (32 * 36 * 4);
#pragma unroll
        for (int q = 0; q < 8; q++) {
            int idx4 = tid + q * 128;           // 0..1023 float4 slots
            int r = idx4 >> 3;
            int h4 = (idx4 & 7) << 2;
            int gr = rowbase + r; if (gr >= NN) gr = NN - 1;
            cpa16(asb + (r * 36 + h4) * 4, &x[gr * HID + hbase + h4]);
        }
#pragma unroll
        for (int q = 0; q < 8; q++) {
            int id = tid + q * 128;             // 0..1023
            int k = id >> 5, hh = id & 31;
            cpa4(bsb + (hh * 36 + k) * 4, &Wd[k * HID + hbase + hh]);
        }
    };

    u64 acc01[8], acc23[8];
#pragma unroll
    for (int i = 0; i < 8; i++) { acc01[i] = 0ULL; acc23[i] = 0ULL; }

    stage(0, 0); CP_COMMIT();

    for (int ch = 0; ch < 8; ch++) {
        int buf = ch & 1;
        if (ch + 1 < 8) { stage(ch + 1, buf ^ 1); CP_COMMIT(); CP_WAIT1(); }
        else            { CP_WAIT0(); }
        __syncthreads();

        const float* A = &As[buf][0];
        const float* B = &Bs[buf][0];
#pragma unroll 8
        for (int hh = 0; hh < 32; hh++) {
            u64 w01 = *(const u64*)&B[hh * 36 + cx * 4];
            u64 w23 = *(const u64*)&B[hh * 36 + cx * 4 + 2];
#pragma unroll
            for (int i = 0; i < 8; i++) {
                float a = A[(ry + 16 * i) * 36 + hh];
                u64 a2 = pk2(a, a);
                ffma2(acc01[i], a2, w01);
                ffma2(acc23[i], a2, w23);
            }
        }
        __syncthreads();
    }

#pragma unroll
    for (int i = 0; i < 8; i++) {
        int r = rowbase + ry + 16 * i;
        if (r < NN) {
            float di = g_dinv[r];
            float4 hsv;
            upk2(hsv.x, hsv.y, acc01[i]);
            upk2(hsv.z, hsv.w, acc23[i]);
            hsv.x *= di; hsv.y *= di; hsv.z *= di; hsv.w *= di;
            *(float4*)&g_hs[r * BN + cx * 4] = hsv;
            float4 ag = make_float4(hsv.x * di, hsv.y * di, hsv.z * di, hsv.w * di);
            *(float4*)&g_agg[r * BN + cx * 4] = ag;
        }
    }
}

// ---------------------------------------------------------------------------
// Edge scatter: agg[col] += hs[row] * dinv[col]
// 8 lanes/edge: one float4 gather + one red.global.add.v4.f32 per lane.
// ---------------------------------------------------------------------------
__global__ __launch_bounds__(256) void k_scatter(const int* __restrict__ rows,
                                                 const int* __restrict__ cols) {
    int t = blockIdx.x * 256 + threadIdx.x;
    int e = t >> 3;
    if (e >= NE) return;
    int j = t & 7;
    int r = rows[e];
    int c = cols[e];
    float dc = __ldg(&g_dinv[c]);
    float4 v = __ldg(((const float4*)g_hs) + (r * 8 + j));
    float4* dst = ((float4*)g_agg) + (c * 8 + j);
    asm volatile("red.global.add.v4.f32 [%0], {%1, %2, %3, %4};"
                 :: "l"(dst), "f"(v.x * dc), "f"(v.y * dc), "f"(v.z * dc), "f"(v.w * dc)
                 : "memory");
}

// ---------------------------------------------------------------------------
// ReLU + bias (float4), then pre-scale for conv2 and re-init agg w/ self-loop
// ---------------------------------------------------------------------------
__global__ __launch_bounds__(256) void k_relu_stage(const float* __restrict__ bd) {
    int i4 = blockIdx.x * blockDim.x + threadIdx.x;   // < NN*BN/4
    int n = i4 >> 3;
    float di = g_dinv[n];
    float4 a = ((const float4*)g_agg)[i4];
    float4 b = ((const float4*)bd)[i4 & 7];
    float4 v;
    v.x = fmaxf(a.x + b.x, 0.0f) * di;
    v.y = fmaxf(a.y + b.y, 0.0f) * di;
    v.z = fmaxf(a.z + b.z, 0.0f) * di;
    v.w = fmaxf(a.w + b.w, 0.0f) * di;
    ((float4*)g_hs)[i4] = v;
    float4 ag = make_float4(v.x * di, v.y * di, v.z * di, v.w * di);
    ((float4*)g_agg)[i4] = ag;
}

// ---------------------------------------------------------------------------
// GEMM2 + epilogue (R10/R11 version -- measured fastest):
// out[n][h] = sum_k agg[n][k] * Wu[h][k] + bu[h] + x[n][h]
// ---------------------------------------------------------------------------
__global__ __launch_bounds__(256) void k_gemm_up(const float* __restrict__ x,
                                                 const float* __restrict__ Wu,
                                                 const float* __restrict__ bu,
                                                 float* __restrict__ out) {
    __shared__ __align__(16) float Bs2[32 * 260];    // [k][h] = Wu[h][k] (33,280 B)
    __shared__ __align__(16) float As2[2][32 * 34];  // [k][r] transposed ( 8,704 B)

    int tid = threadIdx.x;
    int cx = tid & 63;                // cols 4*cx .. 4*cx+3
    int ry = tid >> 6;                // 0..3 (warp-uniform): rows ry*8 .. +7
    int blockrow = blockIdx.x * 128;

    uint32_t bs2b = (uint32_t)__cvta_generic_to_shared(&Bs2[0]);
    uint32_t as2b = (uint32_t)__cvta_generic_to_shared(&As2[0][0]);

    auto stage_tile = [&](int t, int buf) {
        int rb = blockrow + t * 32;
        uint32_t dst = as2b + buf * (32 * 34 * 4);
#pragma unroll
        for (int q = 0; q < 4; q++) {
            int id = tid + q * 256;   // 0..1023
            int k = id & 31;          // lanes: consecutive k -> coalesced src
            int r = id >> 5;
            int gr = rb + r; if (gr >= NN) gr = NN - 1;
            cpa4(dst + (k * 34 + r) * 4, &g_agg[gr * BN + k]);
        }
    };

    // group 0: weights (transposed) + tile 0
#pragma unroll
    for (int q = 0; q < 32; q++) {
        int idx = tid + q * 256;      // 0..8191 = h*32+k
        int h = idx >> 5;
        int k = idx & 31;
        cpa4(bs2b + (k * 260 + h) * 4, &Wu[idx]);
    }
    stage_tile(0, 0);
    CP_COMMIT();

    float4 b4 = *(const float4*)&bu[4 * cx];

    for (int t = 0; t < 4; t++) {
        int buf = t & 1;
        if (t + 1 < 4) { stage_tile(t + 1, buf ^ 1); CP_COMMIT(); CP_WAIT1(); }
        else           { CP_WAIT0(); }
        __syncthreads();

        u64 acc[16];                  // [p(4 row-pairs)][c(4 cols)]
#pragma unroll
        for (int i = 0; i < 16; i++) acc[i] = 0ULL;

        const float* A = &As2[buf][0];
#pragma unroll 8
        for (int k = 0; k < 32; k++) {
            float4 wv = *(const float4*)&Bs2[k * 260 + 4 * cx];
            u64 wd[4];
            wd[0] = pk2(wv.x, wv.x);
            wd[1] = pk2(wv.y, wv.y);
            wd[2] = pk2(wv.z, wv.z);
            wd[3] = pk2(wv.w, wv.w);
            u64 a2[4];
#pragma unroll
            for (int p = 0; p < 4; p++)
                a2[p] = *(const u64*)&A[k * 34 + ry * 8 + 2 * p];
#pragma unroll
            for (int p = 0; p < 4; p++)
#pragma unroll
                for (int c = 0; c < 4; c++)
                    ffma2(acc[p * 4 + c], a2[p], wd[c]);
        }

        int rb = blockrow + t * 32;
#pragma unroll
        for (int p = 0; p < 4; p++) {
            float lo[4], hi[4];
#pragma unroll
            for (int c = 0; c < 4; c++) upk2(lo[c], hi[c], acc[p * 4 + c]);
            int r0 = rb + ry * 8 + 2 * p;
#pragma unroll
            for (int half = 0; half < 2; half++) {
                int r = r0 + half;
                if (r < NN) {
                    const float* v = half ? hi : lo;
                    float4 xv = *(const float4*)&x[r * HID + 4 * cx];
                    float4 o;
                    o.x = v[0] + b4.x + xv.x;
                    o.y = v[1] + b4.y + xv.y;
                    o.z = v[2] + b4.z + xv.z;
                    o.w = v[3] + b4.w + xv.w;
                    *(float4*)&out[r * HID + 4 * cx] = o;
                }
            }
        }
        __syncthreads();
    }
}

// ---------------------------------------------------------------------------
extern "C" void kernel_launch(void* const* d_in, const int* in_sizes, int n_in,
                              void* d_out, int out_size) {
    // Resolve inputs by element count (robust to metadata ordering).
    // edge_index is int32 (JAX x64 disabled -> int64 request yields int32).
    const float* x = 0; const int* ei = 0;
    const float* Wd = 0; const float* bd = 0;
    const float* Wu = 0; const float* bu = 0;
    for (int i = 0; i < n_in; i++) {
        int sz = in_sizes[i];
        if (sz == NN * HID)       x  = (const float*)d_in[i];
        else if (sz == 2 * NE)    ei = (const int*)d_in[i];
        else if (sz == BN * HID) { if (!Wd) Wd = (const float*)d_in[i];
                                   else     Wu = (const float*)d_in[i]; }
        else if (sz == BN)        bd = (const float*)d_in[i];
        else if (sz == HID)       bu = (const float*)d_in[i];
    }
    float* out = (float*)d_out;

    const int* erow = ei;        // edge_index[0] = source
    const int* ecol = ei + NE;   // edge_index[1] = target

    k_init_deg<<<(NN + 255) / 256, 256>>>();
    k_count_deg<<<592, 256>>>(ecol);
    k_finalize_dinv<<<(NN + 255) / 256, 256>>>();

    k_gemm_down<<<(NN + 127) / 128, 128>>>(x, Wd);
    k_scatter<<<(NE * 8) / 256, 256>>>(erow, ecol);
    k_relu_stage<<<(NN * BN / 4 + 255) / 256, 256>>>(bd);
    k_scatter<<<(NE * 8) / 256, 256>>>(erow, ecol);
    k_gemm_up<<<(NN + 127) / 128, 256>>>(x, Wu, bu, out);
}

// round 17
// speedup vs baseline: 1.4030x; 1.4030x over previous
#include <cuda_runtime.h>
#include <cstdint>

#define NN 100000
#define NE 800000
#define HID 256
#define BN 32
#define NB 391                       // ceil(NN/256)

typedef unsigned long long u64;

// Scratch (allocation-free rule: __device__ globals).
__device__ __align__(16) float g_dinv[NN];
__device__ __align__(16) float g_hs[NN * BN];    // hs1 = (x@Wd^T)*dinv[row]
__device__ __align__(16) float g_hs2[NN * BN];   // hs2 = relu(conv1)*dinv[row]
__device__ __align__(16) float g_agg[NN * BN];   // conv2 aggregate (gemm_up input)
__device__ int g_degi[NN];
__device__ int g_rowptr[NN];
__device__ int g_cursor[NN];
__device__ int g_srcE[NE];
__device__ int g_bsum[512];
__device__ int g_boff[512];

// ---- f32x2 packed helpers -------------------------------------------------
__device__ __forceinline__ u64 pk2(float lo, float hi) {
    u64 r; asm("mov.b64 %0, {%1, %2};" : "=l"(r) : "f"(lo), "f"(hi)); return r;
}
__device__ __forceinline__ void upk2(float& lo, float& hi, u64 v) {
    asm("mov.b64 {%0, %1}, %2;" : "=f"(lo), "=f"(hi) : "l"(v));
}
__device__ __forceinline__ void ffma2(u64& d, u64 a, u64 b) {
    asm("fma.rn.f32x2 %0, %1, %2, %0;" : "+l"(d) : "l"(a), "l"(b));
}

// ---- cp.async helpers -----------------------------------------------------
__device__ __forceinline__ void cpa16(uint32_t d, const void* s) {
    asm volatile("cp.async.cg.shared.global [%0], [%1], 16;" :: "r"(d), "l"(s) : "memory");
}
__device__ __forceinline__ void cpa4(uint32_t d, const void* s) {
    asm volatile("cp.async.ca.shared.global [%0], [%1], 4;" :: "r"(d), "l"(s) : "memory");
}
#define CP_COMMIT() asm volatile("cp.async.commit_group;" ::: "memory")
#define CP_WAIT0()  asm volatile("cp.async.wait_group 0;" ::: "memory")
#define CP_WAIT1()  asm volatile("cp.async.wait_group 1;" ::: "memory")

// ===========================================================================
// CSR prologue
// ===========================================================================
__global__ void k_zero_deg() {
    int i = blockIdx.x * blockDim.x + threadIdx.x;
    if (i < NN) g_degi[i] = 0;
}

__global__ __launch_bounds__(256) void k_count(const int* __restrict__ col) {
    for (int e = blockIdx.x * blockDim.x + threadIdx.x; e < NE;
         e += gridDim.x * blockDim.x)
        atomicAdd(&g_degi[col[e]], 1);
}

// per-block sums of deg
__global__ __launch_bounds__(256) void k_block_sum() {
    __shared__ int sd[256];
    int t = threadIdx.x;
    int i = blockIdx.x * 256 + t;
    sd[t] = (i < NN) ? g_degi[i] : 0;
    __syncthreads();
#pragma unroll
    for (int off = 128; off > 0; off >>= 1) {
        if (t < off) sd[t] += sd[t + off];
        __syncthreads();
    }
    if (t == 0) g_bsum[blockIdx.x] = sd[0];
}

// exclusive scan of 391 block sums (single block, 512 threads)
__global__ __launch_bounds__(512) void k_scan_bsum() {
    __shared__ int sd[512];
    int t = threadIdx.x;
    int own = (t < NB) ? g_bsum[t] : 0;
    sd[t] = own;
    __syncthreads();
#pragma unroll
    for (int off = 1; off < 512; off <<= 1) {
        int v = (t >= off) ? sd[t - off] : 0;
        __syncthreads();
        sd[t] += v;
        __syncthreads();
    }
    if (t < NB) g_boff[t] = sd[t] - own;   // exclusive
}

// local scan -> rowptr, cursor, dinv
__global__ __launch_bounds__(256) void k_rowptr() {
    __shared__ int sd[256];
    int t = threadIdx.x;
    int i = blockIdx.x * 256 + t;
    int deg = (i < NN) ? g_degi[i] : 0;
    sd[t] = deg;
    __syncthreads();
#pragma unroll
    for (int off = 1; off < 256; off <<= 1) {
        int v = (t >= off) ? sd[t - off] : 0;
        __syncthreads();
        sd[t] += v;
        __syncthreads();
    }
    if (i < NN) {
        int excl = sd[t] - deg;
        int p = g_boff[blockIdx.x] + excl;
        g_rowptr[i] = p;
        g_cursor[i] = p;
        g_dinv[i] = rsqrtf((float)deg + 1.0f);   // +1 self-loop
    }
}

__global__ __launch_bounds__(256) void k_fill(const int* __restrict__ rows,
                                              const int* __restrict__ cols) {
    for (int e = blockIdx.x * blockDim.x + threadIdx.x; e < NE;
         e += gridDim.x * blockDim.x) {
        int p = atomicAdd(&g_cursor[cols[e]], 1);
        g_srcE[p] = rows[e];
    }
}

// ===========================================================================
// GEMM1 (R9 version): hs = (x @ Wd^T)*dinv      (no agg write anymore)
// ===========================================================================
__global__ __launch_bounds__(128) void k_gemm_down(const float* __restrict__ x,
                                                   const float* __restrict__ Wd) {
    __shared__ __align__(16) float As[2][128 * 36];
    __shared__ __align__(16) float Bs[2][32 * 36];

    int tid = threadIdx.x;
    int cx = tid & 7;
    int ry = tid >> 3;
    int rowbase = blockIdx.x * 128;

    uint32_t as0 = (uint32_t)__cvta_generic_to_shared(&As[0][0]);
    uint32_t bs0 = (uint32_t)__cvta_generic_to_shared(&Bs[0][0]);

    auto stage = [&](int ch, int buf) {
        int hbase = ch * 32;
        uint32_t asb = as0 + buf * (128 * 36 * 4);
        uint32_t bsb = bs0 + buf * (32 * 36 * 4);
#pragma unroll
        for (int q = 0; q < 8; q++) {
            int idx4 = tid + q * 128;
            int r = idx4 >> 3;
            int h4 = (idx4 & 7) << 2;
            int gr = rowbase + r; if (gr >= NN) gr = NN - 1;
            cpa16(asb + (r * 36 + h4) * 4, &x[gr * HID + hbase + h4]);
        }
#pragma unroll
        for (int q = 0; q < 8; q++) {
            int id = tid + q * 128;
            int k = id >> 5, hh = id & 31;
            cpa4(bsb + (hh * 36 + k) * 4, &Wd[k * HID + hbase + hh]);
        }
    };

    u64 acc01[8], acc23[8];
#pragma unroll
    for (int i = 0; i < 8; i++) { acc01[i] = 0ULL; acc23[i] = 0ULL; }

    stage(0, 0); CP_COMMIT();

    for (int ch = 0; ch < 8; ch++) {
        int buf = ch & 1;
        if (ch + 1 < 8) { stage(ch + 1, buf ^ 1); CP_COMMIT(); CP_WAIT1(); }
        else            { CP_WAIT0(); }
        __syncthreads();

        const float* A = &As[buf][0];
        const float* B = &Bs[buf][0];
#pragma unroll 8
        for (int hh = 0; hh < 32; hh++) {
            u64 w01 = *(const u64*)&B[hh * 36 + cx * 4];
            u64 w23 = *(const u64*)&B[hh * 36 + cx * 4 + 2];
#pragma unroll
            for (int i = 0; i < 8; i++) {
                float a = A[(ry + 16 * i) * 36 + hh];
                u64 a2 = pk2(a, a);
                ffma2(acc01[i], a2, w01);
                ffma2(acc23[i], a2, w23);
            }
        }
        __syncthreads();
    }

#pragma unroll
    for (int i = 0; i < 8; i++) {
        int r = rowbase + ry + 16 * i;
        if (r < NN) {
            float di = g_dinv[r];
            float4 hsv;
            upk2(hsv.x, hsv.y, acc01[i]);
            upk2(hsv.z, hsv.w, acc23[i]);
            hsv.x *= di; hsv.y *= di; hsv.z *= di; hsv.w *= di;
            *(float4*)&g_hs[r * BN + cx * 4] = hsv;
        }
    }
}

// ===========================================================================
// Gather-aggregate (warp per node, zero atomics).
// lane = s*8+j: s=edge slot (0..3), j=float4 lane (0..7).
// total[c][j] = feat[c][j] + sum_{e in in(c)} feat[src e][j]
// ===========================================================================
__device__ __forceinline__ float4 f4add(float4 a, float4 b) {
    a.x += b.x; a.y += b.y; a.z += b.z; a.w += b.w; return a;
}
__device__ __forceinline__ float4 warp_reduce_s(float4 v) {
#pragma unroll
    for (int m = 8; m <= 16; m <<= 1) {
        v.x += __shfl_xor_sync(0xffffffffu, v.x, m);
        v.y += __shfl_xor_sync(0xffffffffu, v.y, m);
        v.z += __shfl_xor_sync(0xffffffffu, v.z, m);
        v.w += __shfl_xor_sync(0xffffffffu, v.w, m);
    }
    return v;
}

// conv1 aggregate + bias + relu + pre-scale: g_hs2 = relu(total*dinv + bd)*dinv
__global__ __launch_bounds__(256) void k_gather1(const float* __restrict__ bd) {
    int gw = (blockIdx.x * 256 + threadIdx.x) >> 5;   // global warp = node
    if (gw >= NN) return;
    int lane = threadIdx.x & 31;
    int s = lane >> 3, j = lane & 7;
    int start = g_rowptr[gw];
    int d = g_degi[gw];
    const float4* feat = (const float4*)g_hs;
    float4 sum = make_float4(0.f, 0.f, 0.f, 0.f);
    for (int k = s; k < d; k += 4) {
        int r = __ldg(&g_srcE[start + k]);
        sum = f4add(sum, __ldg(feat + r * 8 + j));
    }
    sum = warp_reduce_s(sum);
    if (s == 0) {
        float di = g_dinv[gw];
        float4 self = feat[gw * 8 + j];
        float4 b = ((const float4*)bd)[j];
        float4 o;
        o.x = fmaxf((sum.x + self.x) * di + b.x, 0.f) * di;
        o.y = fmaxf((sum.y + self.y) * di + b.y, 0.f) * di;
        o.z = fmaxf((sum.z + self.z) * di + b.z, 0.f) * di;
        o.w = fmaxf((sum.w + self.w) * di + b.w, 0.f) * di;
        ((float4*)g_hs2)[gw * 8 + j] = o;
    }
}

// conv2 aggregate: g_agg = total*dinv
__global__ __launch_bounds__(256) void k_gather2() {
    int gw = (blockIdx.x * 256 + threadIdx.x) >> 5;
    if (gw >= NN) return;
    int lane = threadIdx.x & 31;
    int s = lane >> 3, j = lane & 7;
    int start = g_rowptr[gw];
    int d = g_degi[gw];
    const float4* feat = (const float4*)g_hs2;
    float4 sum = make_float4(0.f, 0.f, 0.f, 0.f);
    for (int k = s; k < d; k += 4) {
        int r = __ldg(&g_srcE[start + k]);
        sum = f4add(sum, __ldg(feat + r * 8 + j));
    }
    sum = warp_reduce_s(sum);
    if (s == 0) {
        float di = g_dinv[gw];
        float4 self = feat[gw * 8 + j];
        float4 o;
        o.x = (sum.x + self.x) * di;
        o.y = (sum.y + self.y) * di;
        o.z = (sum.z + self.z) * di;
        o.w = (sum.w + self.w) * di;
        ((float4*)g_agg)[gw * 8 + j] = o;
    }
}

// ===========================================================================
// GEMM2 + epilogue (R10/R11 version): out = agg@Wu^T + bu + x
// ===========================================================================
__global__ __launch_bounds__(256) void k_gemm_up(const float* __restrict__ x,
                                                 const float* __restrict__ Wu,
                                                 const float* __restrict__ bu,
                                                 float* __restrict__ out) {
    __shared__ __align__(16) float Bs2[32 * 260];
    __shared__ __align__(16) float As2[2][32 * 34];

    int tid = threadIdx.x;
    int cx = tid & 63;
    int ry = tid >> 6;
    int blockrow = blockIdx.x * 128;

    uint32_t bs2b = (uint32_t)__cvta_generic_to_shared(&Bs2[0]);
    uint32_t as2b = (uint32_t)__cvta_generic_to_shared(&As2[0][0]);

    auto stage_tile = [&](int t, int buf) {
        int rb = blockrow + t * 32;
        uint32_t dst = as2b + buf * (32 * 34 * 4);
#pragma unroll
        for (int q = 0; q < 4; q++) {
            int id = tid + q * 256;
            int k = id & 31;
            int r = id >> 5;
            int gr = rb + r; if (gr >= NN) gr = NN - 1;
            cpa4(dst + (k * 34 + r) * 4, &g_agg[gr * BN + k]);
        }
    };

#pragma unroll
    for (int q = 0; q < 32; q++) {
        int idx = tid + q * 256;
        int h = idx >> 5;
        int k = idx & 31;
        cpa4(bs2b + (k * 260 + h) * 4, &Wu[idx]);
    }
    stage_tile(0, 0);
    CP_COMMIT();

    float4 b4 = *(const float4*)&bu[4 * cx];

    for (int t = 0; t < 4; t++) {
        int buf = t & 1;
        if (t + 1 < 4) { stage_tile(t + 1, buf ^ 1); CP_COMMIT(); CP_WAIT1(); }
        else           { CP_WAIT0(); }
        __syncthreads();

        u64 acc[16];
#pragma unroll
        for (int i = 0; i < 16; i++) acc[i] = 0ULL;

        const float* A = &As2[buf][0];
#pragma unroll 8
        for (int k = 0; k < 32; k++) {
            float4 wv = *(const float4*)&Bs2[k * 260 + 4 * cx];
            u64 wd[4];
            wd[0] = pk2(wv.x, wv.x);
            wd[1] = pk2(wv.y, wv.y);
            wd[2] = pk2(wv.z, wv.z);
            wd[3] = pk2(wv.w, wv.w);
            u64 a2[4];
#pragma unroll
            for (int p = 0; p < 4; p++)
                a2[p] = *(const u64*)&A[k * 34 + ry * 8 + 2 * p];
#pragma unroll
            for (int p = 0; p < 4; p++)
#pragma unroll
                for (int c = 0; c < 4; c++)
                    ffma2(acc[p * 4 + c], a2[p], wd[c]);
        }

        int rb = blockrow + t * 32;
#pragma unroll
        for (int p = 0; p < 4; p++) {
            float lo[4], hi[4];
#pragma unroll
            for (int c = 0; c < 4; c++) upk2(lo[c], hi[c], acc[p * 4 + c]);
            int r0 = rb + ry * 8 + 2 * p;
#pragma unroll
            for (int half = 0; half < 2; half++) {
                int r = r0 + half;
                if (r < NN) {
                    const float* v = half ? hi : lo;
                    float4 xv = *(const float4*)&x[r * HID + 4 * cx];
                    float4 o;
                    o.x = v[0] + b4.x + xv.x;
                    o.y = v[1] + b4.y + xv.y;
                    o.z = v[2] + b4.z + xv.z;
                    o.w = v[3] + b4.w + xv.w;
                    *(float4*)&out[r * HID + 4 * cx] = o;
                }
            }
        }
        __syncthreads();
    }
}

// ---------------------------------------------------------------------------
extern "C" void kernel_launch(void* const* d_in, const int* in_sizes, int n_in,
                              void* d_out, int out_size) {
    // Resolve inputs by element count (robust to metadata ordering).
    // edge_index is int32 (JAX x64 disabled -> int64 request yields int32).
    const float* x = 0; const int* ei = 0;
    const float* Wd = 0; const float* bd = 0;
    const float* Wu = 0; const float* bu = 0;
    for (int i = 0; i < n_in; i++) {
        int sz = in_sizes[i];
        if (sz == NN * HID)       x  = (const float*)d_in[i];
        else if (sz == 2 * NE)    ei = (const int*)d_in[i];
        else if (sz == BN * HID) { if (!Wd) Wd = (const float*)d_in[i];
                                   else     Wu = (const float*)d_in[i]; }
        else if (sz == BN)        bd = (const float*)d_in[i];
        else if (sz == HID)       bu = (const float*)d_in[i];
    }
    float* out = (float*)d_out;

    const int* erow = ei;        // edge_index[0] = source
    const int* ecol = ei + NE;   // edge_index[1] = target

    // CSR build (also used by conv2; graph is static per call)
    k_zero_deg<<<NB, 256>>>();
    k_count<<<592, 256>>>(ecol);
    k_block_sum<<<NB, 256>>>();
    k_scan_bsum<<<1, 512>>>();
    k_rowptr<<<NB, 256>>>();
    k_fill<<<592, 256>>>(erow, ecol);

    k_gemm_down<<<(NN + 127) / 128, 128>>>(x, Wd);
    k_gather1<<<(NN + 7) / 8, 256>>>(bd);
    k_gather2<<<(NN + 7) / 8, 256>>>();
    k_gemm_up<<<(NN + 127) / 128, 256>>>(x, Wu, bu, out);
}